// round 11
// baseline (speedup 1.0000x reference)
#include <cuda_runtime.h>
#include <cuda_bf16.h>
#include <math.h>
#include <cstdint>

#define T_LEN 24
#define BATCH 16
#define NH    8
#define HDIM  512
#define EDIM  4096
#define TB    (T_LEN*BATCH)     /* 384  */
#define TM1   (T_LEN-1)         /* 23   */
#define ROWS2 (TM1*BATCH)       /* 368  */
#define GK    4096
#define KC    32
#define NCHUNK (GK/KC)          /* 128 */

// ---------------- scratch (static device globals; zero-init, no alloc) ------
__device__ uint32_t g_Asp1[3u*NCHUNK*4096];    // xt split      (6.3 MB)
__device__ uint32_t g_Bsp1[96u*NCHUNK*4096];   // Wqkv split    (201 MB)
__device__ uint32_t g_Asp2[3u*NCHUNK*4096];    // pctx split    (6.3 MB) pad rows stay 0
__device__ uint32_t g_Bsp2[32u*NCHUNK*4096];   // Wo split      (67 MB)
__device__ float    g_qkv[TB*3*EDIM];
__device__ float    g_pooled[ROWS2*EDIM];
__device__ float    g_wbar[TM1*BATCH*NH*T_LEN];

// ---------------- layout helper (shared by writers and reader) ---------------
__device__ __forceinline__ int posw(int row, int kk){
  int s = kk >> 3, kb = kk & 7;
  int perm = (kb < 4) ? (2*kb) : (2*(kb-4) + 1);
  return ((row & 127) * 16) + 8*(s ^ ((row >> 1) & 1)) + perm;
}

__device__ __forceinline__ uint32_t pack_hi(float x, float y, float& rx, float& ry){
  __nv_bfloat16 hx = __float2bfloat16(x), hy = __float2bfloat16(y);
  rx = x - __bfloat162float(hx);
  ry = y - __bfloat162float(hy);
  return ((uint32_t)__bfloat16_as_ushort(hy) << 16) | __bfloat16_as_ushort(hx);
}
__device__ __forceinline__ uint32_t pack_lo(float rx, float ry){
  __nv_bfloat16 lx = __float2bfloat16(rx), ly = __float2bfloat16(ry);
  return ((uint32_t)__bfloat16_as_ushort(ly) << 16) | __bfloat16_as_ushort(lx);
}

// ---------------- split kernels ----------------------------------------------
__global__ __launch_bounds__(256) void k_splitw(const float* __restrict__ W,
                                                uint32_t* __restrict__ dst, int nrows){
  int idx = blockIdx.x*256 + threadIdx.x;
  if (idx >= nrows*2048) return;
  int row = idx >> 11, kp = idx & 2047;
  int c = kp >> 4, kk = kp & 15;
  float2 v = *(const float2*)(W + (size_t)row*GK + 2*kp);
  float rx, ry;
  uint32_t hi = pack_hi(v.x, v.y, rx, ry);
  uint32_t lo = pack_lo(rx, ry);
  size_t base = ((size_t)((row >> 7)*NCHUNK + c))*4096 + posw(row, kk);
  dst[base] = hi; dst[base + 2048] = lo;
}

__global__ __launch_bounds__(256) void k_splitx(const float* __restrict__ x){
  int idx = blockIdx.x*256 + threadIdx.x;
  if (idx >= TB*2048) return;
  int row = idx >> 11, kp = idx & 2047;
  int t = row >> 4, b = row & 15;
  int e = 2*kp, f = e >> 6, n = e & 63;
  const float* xp = x + (((size_t)(b*64 + f))*T_LEN + t)*64 + n;
  float2 v = { xp[0], xp[1] };
  float rx, ry;
  uint32_t hi = pack_hi(v.x, v.y, rx, ry);
  uint32_t lo = pack_lo(rx, ry);
  int c = kp >> 4, kk = kp & 15;
  size_t base = ((size_t)((row >> 7)*NCHUNK + c))*4096 + posw(row, kk);
  g_Asp1[base] = hi; g_Asp1[base + 2048] = lo;
}

// ---------------- cp.async helpers -------------------------------------------
__device__ __forceinline__ uint32_t smem_u32(const void* p){
  uint32_t a;
  asm("{ .reg .u64 t; cvta.to.shared.u64 t, %1; cvt.u32.u64 %0, t; }" : "=r"(a) : "l"(p));
  return a;
}
__device__ __forceinline__ void cpa16(uint32_t s, const void* g){
  asm volatile("cp.async.cg.shared.global [%0], [%1], 16;" :: "r"(s), "l"(g));
}
__device__ __forceinline__ void cpa_commit(){
  asm volatile("cp.async.commit_group;" ::: "memory");
}
__device__ __forceinline__ void cpa_wait1(){
  asm volatile("cp.async.wait_group 1;" ::: "memory");
}

// ---------------- mma.sync wrapper -------------------------------------------
__device__ __forceinline__ void mma16816(float* c,
                                         uint32_t a0, uint32_t a1, uint32_t a2, uint32_t a3,
                                         uint32_t b0, uint32_t b1){
  asm volatile(
    "mma.sync.aligned.m16n8k16.row.col.f32.bf16.bf16.f32 "
    "{%0,%1,%2,%3}, {%4,%5,%6,%7}, {%8,%9}, {%0,%1,%2,%3};"
    : "+f"(c[0]), "+f"(c[1]), "+f"(c[2]), "+f"(c[3])
    : "r"(a0), "r"(a1), "r"(a2), "r"(a3), "r"(b0), "r"(b1));
}

// ---------------- GEMM: C(M,Nn) = A @ B^T + bias (pre-split operands) --------
// stage: [Ahi 8K][Alo 8K][Bhi 8K][Blo 8K] = 32KB; 3 stages = 96KB -> 2 CTA/SM
#define STAGE_B 32768
#define NSTAGE  3
#define GEMM_SMEM (NSTAGE*STAGE_B)

__global__ __launch_bounds__(256,2) void gemm_tc(const uint32_t* __restrict__ Asp,
                                                 const uint32_t* __restrict__ Bsp,
                                                 const float* __restrict__ bias,
                                                 float* __restrict__ C,
                                                 int Nn, int Mvalid){
  extern __shared__ char smem[];
  const uint32_t sb = smem_u32(smem);
  const int tid = threadIdx.x, warp = tid >> 5, lane = tid & 31;
  const int g = lane >> 2, tg = lane & 3;
  const int wm = warp >> 2, wn = warp & 3;
  const int R0 = wm*64, N0 = wn*32;
  const int X = (g >> 1) & 1;
  const uint4* Ag = (const uint4*)(Asp) + (size_t)blockIdx.y*NCHUNK*1024;
  const uint4* Bg = (const uint4*)(Bsp) + (size_t)blockIdx.x*NCHUNK*1024;

  float acc[4][4][4];
  #pragma unroll
  for (int i=0;i<4;i++)
    #pragma unroll
    for (int j=0;j<4;j++)
      #pragma unroll
      for (int r=0;r<4;r++) acc[i][j][r] = 0.f;

  auto issue = [&](int st, int c){
    uint32_t dA = sb + st*STAGE_B + tid*16;
    uint32_t dB = dA + 16384;
    const uint4* a = Ag + (size_t)c*1024 + tid;
    const uint4* b = Bg + (size_t)c*1024 + tid;
    #pragma unroll
    for (int u=0;u<4;u++){
      cpa16(dA + u*4096, a + u*256);
      cpa16(dB + u*4096, b + u*256);
    }
  };

  issue(0,0); cpa_commit();
  issue(1,1); cpa_commit();

  const uint32_t pbs0 = (uint32_t)(8*(0^X) + 2*tg)*4;
  const uint32_t pbs1 = (uint32_t)(8*(1^X) + 2*tg)*4;

  int st = 0, nst = 2;     // stage of chunk c; next stage to fill
  for (int c = 0; c < NCHUNK; c++){
    cpa_wait1();           // chunk c resident (<=1 outstanding group: chunk c+1)
    __syncthreads();       // all warps done computing chunk c-1 (stage nst)
    if (c+2 < NCHUNK) issue(nst, c+2);
    cpa_commit();

    const char* wb = smem + st*STAGE_B;
    #pragma unroll
    for (int s=0;s<2;s++){
      const uint32_t pb = s ? pbs1 : pbs0;
      uint2 bh[4], bl[4];
      #pragma unroll
      for (int j=0;j<4;j++){
        int n = N0 + 8*j + g;
        bh[j] = *(const uint2*)(wb + 16384 + n*64 + pb);
        bl[j] = *(const uint2*)(wb + 24576 + n*64 + pb);
      }
      #pragma unroll
      for (int i=0;i<4;i++){
        int r0 = R0 + 16*i + g;
        uint2 ah0 = *(const uint2*)(wb         + r0*64       + pb);
        uint2 ah1 = *(const uint2*)(wb         + r0*64 + 512 + pb);
        uint2 al0 = *(const uint2*)(wb + 8192  + r0*64       + pb);
        uint2 al1 = *(const uint2*)(wb + 8192  + r0*64 + 512 + pb);
        #pragma unroll
        for (int j=0;j<4;j++){
          mma16816(acc[i][j], ah0.x, ah1.x, ah0.y, ah1.y, bh[j].x, bh[j].y);
          mma16816(acc[i][j], ah0.x, ah1.x, ah0.y, ah1.y, bl[j].x, bl[j].y);
          mma16816(acc[i][j], al0.x, al1.x, al0.y, al1.y, bh[j].x, bh[j].y);
        }
      }
    }
    st = (st+1 == NSTAGE) ? 0 : st+1;
    nst = (nst+1 == NSTAGE) ? 0 : nst+1;
  }

  const int bm = blockIdx.y*128, bn = blockIdx.x*128;
  #pragma unroll
  for (int i=0;i<4;i++){
    int row0 = bm + R0 + 16*i + g;
    int row1 = row0 + 8;
    #pragma unroll
    for (int j=0;j<4;j++){
      int col = bn + N0 + 8*j + 2*tg;
      float b0 = bias[col], b1 = bias[col+1];
      if (row0 < Mvalid){
        float2 o; o.x = acc[i][j][0] + b0; o.y = acc[i][j][1] + b1;
        *(float2*)&C[(size_t)row0*Nn + col] = o;
      }
      if (row1 < Mvalid){
        float2 o; o.x = acc[i][j][2] + b0; o.y = acc[i][j][3] + b1;
        *(float2*)&C[(size_t)row1*Nn + col] = o;
      }
    }
  }
}

// ---------------- small helpers ---------------------------------------------
__device__ __forceinline__ float wsum(float v){
  #pragma unroll
  for (int o=16;o;o>>=1) v += __shfl_xor_sync(0xffffffffu, v, o);
  return v;
}

// ---------------- attention --------------------------------------------------
__global__ __launch_bounds__(256) void k_attn(){
  const int b = blockIdx.x >> 3, h = blockIdx.x & 7;
  __shared__ float Ks[T_LEN][257];
  __shared__ float E[T_LEN][T_LEN+1];
  __shared__ float R[T_LEN][T_LEN+1];
  const int tid = threadIdx.x, warp = tid>>5, lane = tid&31;

  for (int i=tid;i<T_LEN*T_LEN;i+=256) E[i/T_LEN][i%T_LEN] = 0.f;
  __syncthreads();

  for (int c=0;c<2;c++){
    for (int i=tid;i<T_LEN*256;i+=256){
      int k=i>>8, d=i&255;
      Ks[k][d] = g_qkv[((size_t)(k*BATCH+b))*(3*EDIM) + EDIM + h*HDIM + c*256 + d];
    }
    __syncthreads();
    for (int q=warp; q<T_LEN; q+=8){
      const float* qp = &g_qkv[((size_t)(q*BATCH+b))*(3*EDIM) + h*HDIM + c*256];
      float qr[8];
      #pragma unroll
      for (int i=0;i<8;i++) qr[i] = qp[lane + 32*i];
      #pragma unroll 4
      for (int k=0;k<T_LEN;k++){
        float s = 0.f;
        #pragma unroll
        for (int i=0;i<8;i++) s += qr[i]*Ks[k][lane + 32*i];
        s = wsum(s);
        if (lane==0) E[q][k] += s;
      }
    }
    __syncthreads();
  }

  for (int q=warp; q<T_LEN; q+=8){
    float e = 0.f;
    if (lane < T_LEN){
      float bse = E[q][lane]*0.04419417382415922f + ((lane<=q)?1.f:0.f);
      e = __expf(bse);
      E[q][lane] = e;
    }
    float sc = e;
    #pragma unroll
    for (int o=1;o<32;o<<=1){
      float v = __shfl_up_sync(0xffffffffu, sc, o);
      if (lane >= o) sc += v;
    }
    if (lane < T_LEN) R[q][lane] = 1.f / sc;
  }
  __syncthreads();

  for (int t=warp; t<TM1; t+=8){
    if (lane <= t){
      float acc = 0.f;
      #pragma unroll 4
      for (int q=0; q<=t; q++) acc += E[q][lane]*R[q][t];
      g_wbar[(((t*BATCH)+b)*NH + h)*T_LEN + lane] = acc / (float)(t+1);
    }
  }
}

// ---------------- pooled context, split fused into epilogue ------------------
__global__ __launch_bounds__(128) void k_pctx(){
  const int t = blockIdx.x, b = blockIdx.y, h = blockIdx.z;
  __shared__ float w[T_LEN];
  const int tid = threadIdx.x;
  if (tid < T_LEN) w[tid] = (tid<=t) ? g_wbar[((t*BATCH+b)*NH+h)*T_LEN + tid] : 0.f;
  __syncthreads();
  float4 a = make_float4(0.f,0.f,0.f,0.f);
  for (int k=0;k<=t;k++){
    const float* vp = &g_qkv[((size_t)(k*BATCH+b))*(3*EDIM) + 2*EDIM + h*HDIM];
    float4 vv = *(const float4*)(vp + 4*tid);
    float wk = w[k];
    a.x += wk*vv.x; a.y += wk*vv.y; a.z += wk*vv.z; a.w += wk*vv.w;
  }
  const int row = t*BATCH + b;
  const int kp0 = h*256 + 2*tid;
  const int c   = kp0 >> 4;
  const int kk0 = kp0 & 15, kk1 = kk0 + 1;
  float rx, ry;
  uint32_t hi0 = pack_hi(a.x, a.y, rx, ry);
  uint32_t lo0 = pack_lo(rx, ry);
  uint32_t hi1 = pack_hi(a.z, a.w, rx, ry);
  uint32_t lo1 = pack_lo(rx, ry);
  size_t base = ((size_t)((row >> 7)*NCHUNK + c))*4096;
  int p0 = posw(row, kk0), p1 = posw(row, kk1);
  g_Asp2[base + p0] = hi0; g_Asp2[base + 2048 + p0] = lo0;
  g_Asp2[base + p1] = hi1; g_Asp2[base + 2048 + p1] = lo1;
}

// ---------------- head FC ----------------------------------------------------
__global__ __launch_bounds__(256) void k_head(const float* __restrict__ Wfc,
                                              const float* __restrict__ bfc,
                                              float* __restrict__ out){
  const int t = blockIdx.x, b = blockIdx.y;
  __shared__ float P[EDIM];
  __shared__ float Wf[64][65];
  const int tid = threadIdx.x;
  for (int i=tid;i<EDIM;i+=256) P[i] = g_pooled[((size_t)(t*BATCH+b))*EDIM + i];
  for (int i=tid;i<4096;i+=256) Wf[i>>6][i&63] = Wfc[i];
  __syncthreads();
  #pragma unroll 4
  for (int u=0;u<16;u++){
    int idx = tid + 256*u;
    int f = idx >> 6, n = idx & 63;
    float s = bfc[n];
    #pragma unroll
    for (int j=0;j<64;j++) s += P[f*64+j]*Wf[n][j];
    out[(((size_t)(b*64+f))*T_LEN + (t+1))*64 + n] = fmaxf(s, 0.f);
  }
}

// ---------------- copy t=0 slice ---------------------------------------------
__global__ void k_copy0(const float* __restrict__ x, float* __restrict__ out){
  int i = blockIdx.x*blockDim.x + threadIdx.x;
  if (i >= BATCH*64*64) return;
  int n = i & 63, bf = i >> 6;
  size_t a = (size_t)bf*(T_LEN*64) + n;    // t = 0
  out[a] = x[a];
}

// ---------------- launch ------------------------------------------------------
extern "C" void kernel_launch(void* const* d_in, const int* in_sizes, int n_in,
                              void* d_out, int out_size){
  const float* x    = (const float*)d_in[0];
  const float* Wqkv = (const float*)d_in[1];
  const float* bqkv = (const float*)d_in[2];
  const float* Wo   = (const float*)d_in[3];
  const float* bo   = (const float*)d_in[4];
  const float* Wfc  = (const float*)d_in[5];
  const float* bfc  = (const float*)d_in[6];
  float* out = (float*)d_out;

  cudaFuncSetAttribute(gemm_tc, cudaFuncAttributeMaxDynamicSharedMemorySize, GEMM_SMEM);

  uint32_t *Asp1, *Bsp1, *Asp2, *Bsp2;
  float *qkv, *pooled;
  cudaGetSymbolAddress((void**)&Asp1, g_Asp1);
  cudaGetSymbolAddress((void**)&Bsp1, g_Bsp1);
  cudaGetSymbolAddress((void**)&Asp2, g_Asp2);
  cudaGetSymbolAddress((void**)&Bsp2, g_Bsp2);
  cudaGetSymbolAddress((void**)&qkv,    g_qkv);
  cudaGetSymbolAddress((void**)&pooled, g_pooled);

  k_splitx<<<(TB*2048 + 255)/256, 256>>>(x);                       // 0
  k_splitw<<<(12288*2048 + 255)/256, 256>>>(Wqkv, Bsp1, 12288);    // 1
  k_splitw<<<(4096*2048 + 255)/256, 256>>>(Wo, Bsp2, 4096);        // 2
  gemm_tc<<<dim3(96, 3), 256, GEMM_SMEM>>>(Asp1, Bsp1, bqkv, qkv, 3*EDIM, TB);   // 3
  k_attn<<<BATCH*NH, 256>>>();                                     // 4
  k_pctx<<<dim3(TM1, BATCH, NH), 128>>>();                         // 5
  gemm_tc<<<dim3(32, 3), 256, GEMM_SMEM>>>(Asp2, Bsp2, bo, pooled, EDIM, ROWS2); // 6
  k_head<<<dim3(TM1, BATCH), 256>>>(Wfc, bfc, out);                // 7
  k_copy0<<<(BATCH*64*64 + 255)/256, 256>>>(x, out);               // 8
}

// round 12
// speedup vs baseline: 1.3892x; 1.3892x over previous
#include <cuda_runtime.h>
#include <cuda_bf16.h>
#include <math.h>
#include <cstdint>

#define T_LEN 24
#define BATCH 16
#define NH    8
#define HDIM  512
#define EDIM  4096
#define TB    (T_LEN*BATCH)     /* 384  */
#define TM1   (T_LEN-1)         /* 23   */
#define ROWS2 (TM1*BATCH)       /* 368  */
#define GK    4096
#define KC    32
#define NCHUNK (GK/KC)          /* 128 */

// ---------------- scratch (static device globals; zero-init, no alloc) ------
__device__ uint32_t g_Asp1[3u*NCHUNK*4096];    // xt split      (6.3 MB)
__device__ uint32_t g_Bsp1[96u*NCHUNK*4096];   // Wqkv split    (201 MB)
__device__ uint32_t g_Asp2[3u*NCHUNK*4096];    // pctx split    (6.3 MB) pad rows stay 0
__device__ uint32_t g_Bsp2[32u*NCHUNK*4096];   // Wo split      (67 MB)
__device__ float    g_qkv[TB*3*EDIM];
__device__ float    g_pooled[ROWS2*EDIM];
__device__ float    g_wbar[TM1*BATCH*NH*T_LEN];

// ---------------- layout helper (shared by writers and reader) ---------------
__device__ __forceinline__ int posw(int row, int kk){
  int s = kk >> 3, kb = kk & 7;
  int perm = (kb < 4) ? (2*kb) : (2*(kb-4) + 1);
  return ((row & 127) * 16) + 8*(s ^ ((row >> 1) & 1)) + perm;
}

__device__ __forceinline__ uint32_t pack_hi(float x, float y, float& rx, float& ry){
  __nv_bfloat16 hx = __float2bfloat16(x), hy = __float2bfloat16(y);
  rx = x - __bfloat162float(hx);
  ry = y - __bfloat162float(hy);
  return ((uint32_t)__bfloat16_as_ushort(hy) << 16) | __bfloat16_as_ushort(hx);
}
__device__ __forceinline__ uint32_t pack_lo(float rx, float ry){
  __nv_bfloat16 lx = __float2bfloat16(rx), ly = __float2bfloat16(ry);
  return ((uint32_t)__bfloat16_as_ushort(ly) << 16) | __bfloat16_as_ushort(lx);
}

// ---------------- split kernels ----------------------------------------------
__global__ __launch_bounds__(256) void k_splitw(const float* __restrict__ W,
                                                uint32_t* __restrict__ dst, int nrows){
  int idx = blockIdx.x*256 + threadIdx.x;
  if (idx >= nrows*2048) return;
  int row = idx >> 11, kp = idx & 2047;
  int c = kp >> 4, kk = kp & 15;
  float2 v = *(const float2*)(W + (size_t)row*GK + 2*kp);
  float rx, ry;
  uint32_t hi = pack_hi(v.x, v.y, rx, ry);
  uint32_t lo = pack_lo(rx, ry);
  size_t base = ((size_t)((row >> 7)*NCHUNK + c))*4096 + posw(row, kk);
  dst[base] = hi; dst[base + 2048] = lo;
}

__global__ __launch_bounds__(256) void k_splitx(const float* __restrict__ x){
  int idx = blockIdx.x*256 + threadIdx.x;
  if (idx >= TB*2048) return;
  int row = idx >> 11, kp = idx & 2047;
  int t = row >> 4, b = row & 15;
  int e = 2*kp, f = e >> 6, n = e & 63;
  const float* xp = x + (((size_t)(b*64 + f))*T_LEN + t)*64 + n;
  float2 v = { xp[0], xp[1] };
  float rx, ry;
  uint32_t hi = pack_hi(v.x, v.y, rx, ry);
  uint32_t lo = pack_lo(rx, ry);
  int c = kp >> 4, kk = kp & 15;
  size_t base = ((size_t)((row >> 7)*NCHUNK + c))*4096 + posw(row, kk);
  g_Asp1[base] = hi; g_Asp1[base + 2048] = lo;
}

// ---------------- cp.async helpers -------------------------------------------
__device__ __forceinline__ uint32_t smem_u32(const void* p){
  uint32_t a;
  asm("{ .reg .u64 t; cvta.to.shared.u64 t, %1; cvt.u32.u64 %0, t; }" : "=r"(a) : "l"(p));
  return a;
}
__device__ __forceinline__ void cpa16(uint32_t s, const void* g){
  asm volatile("cp.async.cg.shared.global [%0], [%1], 16;" :: "r"(s), "l"(g));
}
__device__ __forceinline__ void cpa_commit(){
  asm volatile("cp.async.commit_group;" ::: "memory");
}
__device__ __forceinline__ void cpa_wait2(){
  asm volatile("cp.async.wait_group 2;" ::: "memory");
}

// ---------------- mma.sync wrapper -------------------------------------------
__device__ __forceinline__ void mma16816(float* c,
                                         uint32_t a0, uint32_t a1, uint32_t a2, uint32_t a3,
                                         uint32_t b0, uint32_t b1){
  asm volatile(
    "mma.sync.aligned.m16n8k16.row.col.f32.bf16.bf16.f32 "
    "{%0,%1,%2,%3}, {%4,%5,%6,%7}, {%8,%9}, {%0,%1,%2,%3};"
    : "+f"(c[0]), "+f"(c[1]), "+f"(c[2]), "+f"(c[3])
    : "r"(a0), "r"(a1), "r"(a2), "r"(a3), "r"(b0), "r"(b1));
}

// ---------------- GEMM: C(M,Nn) = A @ B^T + bias (pre-split operands) --------
// stage: [Ahi 8K][Alo 8K][Bhi 8K][Blo 8K] = 32KB; 4 stages = 128KB (1 CTA/SM)
#define STAGE_B 32768
#define GEMM_SMEM (4*STAGE_B)

__global__ __launch_bounds__(256,1) void gemm_tc(const uint32_t* __restrict__ Asp,
                                                 const uint32_t* __restrict__ Bsp,
                                                 const float* __restrict__ bias,
                                                 float* __restrict__ C,
                                                 int Nn, int Mvalid){
  extern __shared__ char smem[];
  const uint32_t sb = smem_u32(smem);
  const int tid = threadIdx.x, warp = tid >> 5, lane = tid & 31;
  const int g = lane >> 2, tg = lane & 3;
  const int wm = warp >> 2, wn = warp & 3;
  const int R0 = wm*64, N0 = wn*32;
  const int X = (g >> 1) & 1;
  const uint4* Ag = (const uint4*)(Asp) + (size_t)blockIdx.y*NCHUNK*1024;
  const uint4* Bg = (const uint4*)(Bsp) + (size_t)blockIdx.x*NCHUNK*1024;

  float acc[4][4][4];
  #pragma unroll
  for (int i=0;i<4;i++)
    #pragma unroll
    for (int j=0;j<4;j++)
      #pragma unroll
      for (int r=0;r<4;r++) acc[i][j][r] = 0.f;

  auto issue = [&](int st, int c){
    uint32_t dA = sb + st*STAGE_B + tid*16;
    uint32_t dB = dA + 16384;
    const uint4* a = Ag + (size_t)c*1024 + tid;
    const uint4* b = Bg + (size_t)c*1024 + tid;
    #pragma unroll
    for (int u=0;u<4;u++){
      cpa16(dA + u*4096, a + u*256);
      cpa16(dB + u*4096, b + u*256);
    }
  };

  issue(0,0); cpa_commit();
  issue(1,1); cpa_commit();
  issue(2,2); cpa_commit();

  const uint32_t pbs0 = (uint32_t)(8*(0^X) + 2*tg)*4;
  const uint32_t pbs1 = (uint32_t)(8*(1^X) + 2*tg)*4;

  for (int c = 0; c < NCHUNK; c++){
    const int st = c & 3;
    cpa_wait2();
    __syncthreads();
    if (c+3 < NCHUNK) issue((c+3)&3, c+3);
    cpa_commit();

    const char* wb = smem + st*STAGE_B;
    #pragma unroll
    for (int s=0;s<2;s++){
      const uint32_t pb = s ? pbs1 : pbs0;
      // load ALL fragments for this k16 step first
      uint2 bh[4], bl[4], ah0[4], ah1[4], al0[4], al1[4];
      #pragma unroll
      for (int j=0;j<4;j++){
        int n = N0 + 8*j + g;
        bh[j] = *(const uint2*)(wb + 16384 + n*64 + pb);
        bl[j] = *(const uint2*)(wb + 24576 + n*64 + pb);
      }
      #pragma unroll
      for (int i=0;i<4;i++){
        int r0 = R0 + 16*i + g;
        ah0[i] = *(const uint2*)(wb        + r0*64       + pb);
        ah1[i] = *(const uint2*)(wb        + r0*64 + 512 + pb);
        al0[i] = *(const uint2*)(wb + 8192 + r0*64       + pb);
        al1[i] = *(const uint2*)(wb + 8192 + r0*64 + 512 + pb);
      }
      // product-major issue order: same-acc reuse distance = 16 MMAs
      #pragma unroll
      for (int i=0;i<4;i++)
        #pragma unroll
        for (int j=0;j<4;j++)
          mma16816(acc[i][j], ah0[i].x, ah1[i].x, ah0[i].y, ah1[i].y, bh[j].x, bh[j].y);
      #pragma unroll
      for (int i=0;i<4;i++)
        #pragma unroll
        for (int j=0;j<4;j++)
          mma16816(acc[i][j], ah0[i].x, ah1[i].x, ah0[i].y, ah1[i].y, bl[j].x, bl[j].y);
      #pragma unroll
      for (int i=0;i<4;i++)
        #pragma unroll
        for (int j=0;j<4;j++)
          mma16816(acc[i][j], al0[i].x, al1[i].x, al0[i].y, al1[i].y, bh[j].x, bh[j].y);
    }
  }

  const int bm = blockIdx.y*128, bn = blockIdx.x*128;
  #pragma unroll
  for (int i=0;i<4;i++){
    int row0 = bm + R0 + 16*i + g;
    int row1 = row0 + 8;
    #pragma unroll
    for (int j=0;j<4;j++){
      int col = bn + N0 + 8*j + 2*tg;
      float b0 = bias[col], b1 = bias[col+1];
      if (row0 < Mvalid){
        float2 o; o.x = acc[i][j][0] + b0; o.y = acc[i][j][1] + b1;
        *(float2*)&C[(size_t)row0*Nn + col] = o;
      }
      if (row1 < Mvalid){
        float2 o; o.x = acc[i][j][2] + b0; o.y = acc[i][j][3] + b1;
        *(float2*)&C[(size_t)row1*Nn + col] = o;
      }
    }
  }
}

// ---------------- small helpers ---------------------------------------------
__device__ __forceinline__ float wsum(float v){
  #pragma unroll
  for (int o=16;o;o>>=1) v += __shfl_xor_sync(0xffffffffu, v, o);
  return v;
}

// ---------------- attention --------------------------------------------------
__global__ __launch_bounds__(256) void k_attn(){
  const int b = blockIdx.x >> 3, h = blockIdx.x & 7;
  __shared__ float Ks[T_LEN][257];
  __shared__ float E[T_LEN][T_LEN+1];
  __shared__ float R[T_LEN][T_LEN+1];
  const int tid = threadIdx.x, warp = tid>>5, lane = tid&31;

  for (int i=tid;i<T_LEN*T_LEN;i+=256) E[i/T_LEN][i%T_LEN] = 0.f;
  __syncthreads();

  for (int c=0;c<2;c++){
    for (int i=tid;i<T_LEN*256;i+=256){
      int k=i>>8, d=i&255;
      Ks[k][d] = g_qkv[((size_t)(k*BATCH+b))*(3*EDIM) + EDIM + h*HDIM + c*256 + d];
    }
    __syncthreads();
    for (int q=warp; q<T_LEN; q+=8){
      const float* qp = &g_qkv[((size_t)(q*BATCH+b))*(3*EDIM) + h*HDIM + c*256];
      float qr[8];
      #pragma unroll
      for (int i=0;i<8;i++) qr[i] = qp[lane + 32*i];
      #pragma unroll 4
      for (int k=0;k<T_LEN;k++){
        float s = 0.f;
        #pragma unroll
        for (int i=0;i<8;i++) s += qr[i]*Ks[k][lane + 32*i];
        s = wsum(s);
        if (lane==0) E[q][k] += s;
      }
    }
    __syncthreads();
  }

  for (int q=warp; q<T_LEN; q+=8){
    float e = 0.f;
    if (lane < T_LEN){
      float bse = E[q][lane]*0.04419417382415922f + ((lane<=q)?1.f:0.f);
      e = __expf(bse);
      E[q][lane] = e;
    }
    float sc = e;
    #pragma unroll
    for (int o=1;o<32;o<<=1){
      float v = __shfl_up_sync(0xffffffffu, sc, o);
      if (lane >= o) sc += v;
    }
    if (lane < T_LEN) R[q][lane] = 1.f / sc;
  }
  __syncthreads();

  for (int t=warp; t<TM1; t+=8){
    if (lane <= t){
      float acc = 0.f;
      #pragma unroll 4
      for (int q=0; q<=t; q++) acc += E[q][lane]*R[q][t];
      g_wbar[(((t*BATCH)+b)*NH + h)*T_LEN + lane] = acc / (float)(t+1);
    }
  }
}

// ---------------- pooled context, split fused into epilogue ------------------
__global__ __launch_bounds__(128) void k_pctx(){
  const int t = blockIdx.x, b = blockIdx.y, h = blockIdx.z;
  __shared__ float w[T_LEN];
  const int tid = threadIdx.x;
  if (tid < T_LEN) w[tid] = (tid<=t) ? g_wbar[((t*BATCH+b)*NH+h)*T_LEN + tid] : 0.f;
  __syncthreads();
  float4 a = make_float4(0.f,0.f,0.f,0.f);
  for (int k=0;k<=t;k++){
    const float* vp = &g_qkv[((size_t)(k*BATCH+b))*(3*EDIM) + 2*EDIM + h*HDIM];
    float4 vv = *(const float4*)(vp + 4*tid);
    float wk = w[k];
    a.x += wk*vv.x; a.y += wk*vv.y; a.z += wk*vv.z; a.w += wk*vv.w;
  }
  const int row = t*BATCH + b;
  const int kp0 = h*256 + 2*tid;
  const int c   = kp0 >> 4;
  const int kk0 = kp0 & 15, kk1 = kk0 + 1;
  float rx, ry;
  uint32_t hi0 = pack_hi(a.x, a.y, rx, ry);
  uint32_t lo0 = pack_lo(rx, ry);
  uint32_t hi1 = pack_hi(a.z, a.w, rx, ry);
  uint32_t lo1 = pack_lo(rx, ry);
  size_t base = ((size_t)((row >> 7)*NCHUNK + c))*4096;
  int p0 = posw(row, kk0), p1 = posw(row, kk1);
  g_Asp2[base + p0] = hi0; g_Asp2[base + 2048 + p0] = lo0;
  g_Asp2[base + p1] = hi1; g_Asp2[base + 2048 + p1] = lo1;
}

// ---------------- head FC ----------------------------------------------------
__global__ __launch_bounds__(256) void k_head(const float* __restrict__ Wfc,
                                              const float* __restrict__ bfc,
                                              float* __restrict__ out){
  const int t = blockIdx.x, b = blockIdx.y;
  __shared__ float P[EDIM];
  __shared__ float Wf[64][65];
  const int tid = threadIdx.x;
  for (int i=tid;i<EDIM;i+=256) P[i] = g_pooled[((size_t)(t*BATCH+b))*EDIM + i];
  for (int i=tid;i<4096;i+=256) Wf[i>>6][i&63] = Wfc[i];
  __syncthreads();
  #pragma unroll 4
  for (int u=0;u<16;u++){
    int idx = tid + 256*u;
    int f = idx >> 6, n = idx & 63;
    float s = bfc[n];
    #pragma unroll
    for (int j=0;j<64;j++) s += P[f*64+j]*Wf[n][j];
    out[(((size_t)(b*64+f))*T_LEN + (t+1))*64 + n] = fmaxf(s, 0.f);
  }
}

// ---------------- copy t=0 slice ---------------------------------------------
__global__ void k_copy0(const float* __restrict__ x, float* __restrict__ out){
  int i = blockIdx.x*blockDim.x + threadIdx.x;
  if (i >= BATCH*64*64) return;
  int n = i & 63, bf = i >> 6;
  size_t a = (size_t)bf*(T_LEN*64) + n;    // t = 0
  out[a] = x[a];
}

// ---------------- launch ------------------------------------------------------
extern "C" void kernel_launch(void* const* d_in, const int* in_sizes, int n_in,
                              void* d_out, int out_size){
  const float* x    = (const float*)d_in[0];
  const float* Wqkv = (const float*)d_in[1];
  const float* bqkv = (const float*)d_in[2];
  const float* Wo   = (const float*)d_in[3];
  const float* bo   = (const float*)d_in[4];
  const float* Wfc  = (const float*)d_in[5];
  const float* bfc  = (const float*)d_in[6];
  float* out = (float*)d_out;

  cudaFuncSetAttribute(gemm_tc, cudaFuncAttributeMaxDynamicSharedMemorySize, GEMM_SMEM);

  uint32_t *Asp1, *Bsp1, *Asp2, *Bsp2;
  float *qkv, *pooled;
  cudaGetSymbolAddress((void**)&Asp1, g_Asp1);
  cudaGetSymbolAddress((void**)&Bsp1, g_Bsp1);
  cudaGetSymbolAddress((void**)&Asp2, g_Asp2);
  cudaGetSymbolAddress((void**)&Bsp2, g_Bsp2);
  cudaGetSymbolAddress((void**)&qkv,    g_qkv);
  cudaGetSymbolAddress((void**)&pooled, g_pooled);

  k_splitx<<<(TB*2048 + 255)/256, 256>>>(x);                       // 0
  k_splitw<<<(12288*2048 + 255)/256, 256>>>(Wqkv, Bsp1, 12288);    // 1
  k_splitw<<<(4096*2048 + 255)/256, 256>>>(Wo, Bsp2, 4096);        // 2
  gemm_tc<<<dim3(96, 3), 256, GEMM_SMEM>>>(Asp1, Bsp1, bqkv, qkv, 3*EDIM, TB);   // 3
  k_attn<<<BATCH*NH, 256>>>();                                     // 4
  k_pctx<<<dim3(TM1, BATCH, NH), 128>>>();                         // 5
  gemm_tc<<<dim3(32, 3), 256, GEMM_SMEM>>>(Asp2, Bsp2, bo, pooled, EDIM, ROWS2); // 6
  k_head<<<dim3(TM1, BATCH), 256>>>(Wfc, bfc, out);                // 7
  k_copy0<<<(BATCH*64*64 + 255)/256, 256>>>(x, out);               // 8
}

// round 13
// speedup vs baseline: 1.4989x; 1.0790x over previous
#include <cuda_runtime.h>
#include <cuda_bf16.h>
#include <math.h>
#include <cstdint>

#define T_LEN 24
#define BATCH 16
#define NH    8
#define HDIM  512
#define EDIM  4096
#define TB    (T_LEN*BATCH)     /* 384  */
#define TM1   (T_LEN-1)         /* 23   */
#define ROWS2 (TM1*BATCH)       /* 368  */
#define GK    4096
#define KC    32
#define NCHUNK (GK/KC)          /* 128 */

// ---------------- scratch (static device globals; zero-init, no alloc) ------
__device__ uint32_t g_Asp1[3u*NCHUNK*4096];    // xt split      (6.3 MB)
__device__ uint32_t g_Bsp1[96u*NCHUNK*4096];   // Wqkv split    (201 MB)
__device__ uint32_t g_Asp2[3u*NCHUNK*4096];    // pctx split    (6.3 MB) pad rows stay 0
__device__ uint32_t g_Bsp2[32u*NCHUNK*4096];   // Wo split      (67 MB)
__device__ float    g_qkv[TB*3*EDIM];
__device__ float    g_pooled[2u*ROWS2*EDIM];   // two split-K partials
__device__ float    g_wbar[TM1*BATCH*NH*T_LEN];

// ---------------- layout helper (shared by writers and reader) ---------------
__device__ __forceinline__ int posw(int row, int kk){
  int s = kk >> 3, kb = kk & 7;
  int perm = (kb < 4) ? (2*kb) : (2*(kb-4) + 1);
  return ((row & 127) * 16) + 8*(s ^ ((row >> 1) & 1)) + perm;
}

__device__ __forceinline__ uint32_t pack_hi(float x, float y, float& rx, float& ry){
  __nv_bfloat16 hx = __float2bfloat16(x), hy = __float2bfloat16(y);
  rx = x - __bfloat162float(hx);
  ry = y - __bfloat162float(hy);
  return ((uint32_t)__bfloat16_as_ushort(hy) << 16) | __bfloat16_as_ushort(hx);
}
__device__ __forceinline__ uint32_t pack_lo(float rx, float ry){
  __nv_bfloat16 lx = __float2bfloat16(rx), ly = __float2bfloat16(ry);
  return ((uint32_t)__bfloat16_as_ushort(ly) << 16) | __bfloat16_as_ushort(lx);
}

// ---------------- split kernels (float4 per thread) --------------------------
__global__ __launch_bounds__(256) void k_splitw(const float* __restrict__ W,
                                                uint32_t* __restrict__ dst, int nrows){
  int idx = blockIdx.x*256 + threadIdx.x;          // float4 index
  if (idx >= nrows*1024) return;
  int row = idx >> 10, q = idx & 1023;
  float4 v = *(const float4*)(W + (size_t)row*GK + 4*q);
  int kk0 = (2*q) & 15, c = q >> 3;
  float rx, ry, rz, rw;
  uint32_t hi0 = pack_hi(v.x, v.y, rx, ry);
  uint32_t hi1 = pack_hi(v.z, v.w, rz, rw);
  uint32_t lo0 = pack_lo(rx, ry);
  uint32_t lo1 = pack_lo(rz, rw);
  size_t base = ((size_t)((row >> 7)*NCHUNK + c))*4096;
  int p0 = posw(row, kk0), p1 = posw(row, kk0+1);
  dst[base + p0] = hi0;        dst[base + p1] = hi1;
  dst[base + 2048 + p0] = lo0; dst[base + 2048 + p1] = lo1;
}

__global__ __launch_bounds__(256) void k_splitx(const float* __restrict__ x){
  int idx = blockIdx.x*256 + threadIdx.x;          // float4 index
  if (idx >= TB*1024) return;
  int row = idx >> 10, q = idx & 1023;
  int t = row >> 4, b = row & 15;
  int e = 4*q, f = e >> 6, n = e & 63;
  float4 v = *(const float4*)(x + (((size_t)(b*64 + f))*T_LEN + t)*64 + n);
  int kk0 = (2*q) & 15, c = q >> 3;
  float rx, ry, rz, rw;
  uint32_t hi0 = pack_hi(v.x, v.y, rx, ry);
  uint32_t hi1 = pack_hi(v.z, v.w, rz, rw);
  uint32_t lo0 = pack_lo(rx, ry);
  uint32_t lo1 = pack_lo(rz, rw);
  size_t base = ((size_t)((row >> 7)*NCHUNK + c))*4096;
  int p0 = posw(row, kk0), p1 = posw(row, kk0+1);
  g_Asp1[base + p0] = hi0;        g_Asp1[base + p1] = hi1;
  g_Asp1[base + 2048 + p0] = lo0; g_Asp1[base + 2048 + p1] = lo1;
}

// ---------------- cp.async helpers -------------------------------------------
__device__ __forceinline__ uint32_t smem_u32(const void* p){
  uint32_t a;
  asm("{ .reg .u64 t; cvta.to.shared.u64 t, %1; cvt.u32.u64 %0, t; }" : "=r"(a) : "l"(p));
  return a;
}
__device__ __forceinline__ void cpa16(uint32_t s, const void* g){
  asm volatile("cp.async.cg.shared.global [%0], [%1], 16;" :: "r"(s), "l"(g));
}
__device__ __forceinline__ void cpa_commit(){
  asm volatile("cp.async.commit_group;" ::: "memory");
}
__device__ __forceinline__ void cpa_wait2(){
  asm volatile("cp.async.wait_group 2;" ::: "memory");
}

// ---------------- mma.sync wrapper -------------------------------------------
__device__ __forceinline__ void mma16816(float* c,
                                         uint32_t a0, uint32_t a1, uint32_t a2, uint32_t a3,
                                         uint32_t b0, uint32_t b1){
  asm volatile(
    "mma.sync.aligned.m16n8k16.row.col.f32.bf16.bf16.f32 "
    "{%0,%1,%2,%3}, {%4,%5,%6,%7}, {%8,%9}, {%0,%1,%2,%3};"
    : "+f"(c[0]), "+f"(c[1]), "+f"(c[2]), "+f"(c[3])
    : "r"(a0), "r"(a1), "r"(a2), "r"(a3), "r"(b0), "r"(b1));
}

// ---------------- GEMM: C(M,Nn) = A @ B^T (+bias) (pre-split operands) -------
// grid: (bm_blocks, bn_blocks, ksplit). bm fastest -> consecutive CTAs share B.
// stage: [Ahi 8K][Alo 8K][Bhi 8K][Blo 8K] = 32KB; 4 stages = 128KB (1 CTA/SM)
#define STAGE_B 32768
#define GEMM_SMEM (4*STAGE_B)

__global__ __launch_bounds__(256,1) void gemm_tc(const uint32_t* __restrict__ Asp,
                                                 const uint32_t* __restrict__ Bsp,
                                                 const float* __restrict__ bias,
                                                 float* __restrict__ C,
                                                 int Nn, int Mvalid,
                                                 int nchunks, int zstride){
  extern __shared__ char smem[];
  const uint32_t sb = smem_u32(smem);
  const int tid = threadIdx.x, warp = tid >> 5, lane = tid & 31;
  const int g = lane >> 2, tg = lane & 3;
  const int wm = warp >> 2, wn = warp & 3;
  const int R0 = wm*64, N0 = wn*32;
  const int X = (g >> 1) & 1;
  const int z = blockIdx.z;
  const int koff = z * nchunks;                 // chunk offset of this K-split
  const uint4* Ag = (const uint4*)(Asp) + ((size_t)blockIdx.x*NCHUNK + koff)*1024;
  const uint4* Bg = (const uint4*)(Bsp) + ((size_t)blockIdx.y*NCHUNK + koff)*1024;
  const float* bp = (z == 0) ? bias : nullptr;
  float* Cz = C + (size_t)z*zstride;

  float acc[4][4][4];
  #pragma unroll
  for (int i=0;i<4;i++)
    #pragma unroll
    for (int j=0;j<4;j++)
      #pragma unroll
      for (int r=0;r<4;r++) acc[i][j][r] = 0.f;

  auto issue = [&](int st, int c){
    uint32_t dA = sb + st*STAGE_B + tid*16;
    uint32_t dB = dA + 16384;
    const uint4* a = Ag + (size_t)c*1024 + tid;
    const uint4* b = Bg + (size_t)c*1024 + tid;
    #pragma unroll
    for (int u=0;u<4;u++){
      cpa16(dA + u*4096, a + u*256);
      cpa16(dB + u*4096, b + u*256);
    }
  };

  issue(0,0); cpa_commit();
  issue(1,1); cpa_commit();
  issue(2,2); cpa_commit();

  const uint32_t pbs0 = (uint32_t)(8*(0^X) + 2*tg)*4;
  const uint32_t pbs1 = (uint32_t)(8*(1^X) + 2*tg)*4;

  for (int c = 0; c < nchunks; c++){
    const int st = c & 3;
    cpa_wait2();
    __syncthreads();
    if (c+3 < nchunks) issue((c+3)&3, c+3);
    cpa_commit();

    const char* wb = smem + st*STAGE_B;
    #pragma unroll
    for (int s=0;s<2;s++){
      const uint32_t pb = s ? pbs1 : pbs0;
      uint2 bh[4], bl[4];
      #pragma unroll
      for (int j=0;j<4;j++){
        int n = N0 + 8*j + g;
        bh[j] = *(const uint2*)(wb + 16384 + n*64 + pb);
        bl[j] = *(const uint2*)(wb + 24576 + n*64 + pb);
      }
      #pragma unroll
      for (int i=0;i<4;i++){
        int r0 = R0 + 16*i + g;
        uint2 ah0 = *(const uint2*)(wb         + r0*64       + pb);
        uint2 ah1 = *(const uint2*)(wb         + r0*64 + 512 + pb);
        uint2 al0 = *(const uint2*)(wb + 8192  + r0*64       + pb);
        uint2 al1 = *(const uint2*)(wb + 8192  + r0*64 + 512 + pb);
        #pragma unroll
        for (int j=0;j<4;j++){
          mma16816(acc[i][j], ah0.x, ah1.x, ah0.y, ah1.y, bh[j].x, bh[j].y);
          mma16816(acc[i][j], ah0.x, ah1.x, ah0.y, ah1.y, bl[j].x, bl[j].y);
          mma16816(acc[i][j], al0.x, al1.x, al0.y, al1.y, bh[j].x, bh[j].y);
        }
      }
    }
  }

  const int bm = blockIdx.x*128, bn = blockIdx.y*128;
  #pragma unroll
  for (int i=0;i<4;i++){
    int row0 = bm + R0 + 16*i + g;
    int row1 = row0 + 8;
    #pragma unroll
    for (int j=0;j<4;j++){
      int col = bn + N0 + 8*j + 2*tg;
      float b0 = bp ? bp[col]   : 0.f;
      float b1 = bp ? bp[col+1] : 0.f;
      if (row0 < Mvalid){
        float2 o; o.x = acc[i][j][0] + b0; o.y = acc[i][j][1] + b1;
        *(float2*)&Cz[(size_t)row0*Nn + col] = o;
      }
      if (row1 < Mvalid){
        float2 o; o.x = acc[i][j][2] + b0; o.y = acc[i][j][3] + b1;
        *(float2*)&Cz[(size_t)row1*Nn + col] = o;
      }
    }
  }
}

// ---------------- small helpers ---------------------------------------------
__device__ __forceinline__ float wsum(float v){
  #pragma unroll
  for (int o=16;o;o>>=1) v += __shfl_xor_sync(0xffffffffu, v, o);
  return v;
}

// ---------------- attention --------------------------------------------------
__global__ __launch_bounds__(256) void k_attn(){
  const int b = blockIdx.x >> 3, h = blockIdx.x & 7;
  __shared__ float Ks[T_LEN][257];
  __shared__ float E[T_LEN][T_LEN+1];
  __shared__ float R[T_LEN][T_LEN+1];
  const int tid = threadIdx.x, warp = tid>>5, lane = tid&31;

  for (int i=tid;i<T_LEN*T_LEN;i+=256) E[i/T_LEN][i%T_LEN] = 0.f;
  __syncthreads();

  for (int c=0;c<2;c++){
    for (int i=tid;i<T_LEN*256;i+=256){
      int k=i>>8, d=i&255;
      Ks[k][d] = g_qkv[((size_t)(k*BATCH+b))*(3*EDIM) + EDIM + h*HDIM + c*256 + d];
    }
    __syncthreads();
    for (int q=warp; q<T_LEN; q+=8){
      const float* qp = &g_qkv[((size_t)(q*BATCH+b))*(3*EDIM) + h*HDIM + c*256];
      float qr[8];
      #pragma unroll
      for (int i=0;i<8;i++) qr[i] = qp[lane + 32*i];
      #pragma unroll 4
      for (int k=0;k<T_LEN;k++){
        float s = 0.f;
        #pragma unroll
        for (int i=0;i<8;i++) s += qr[i]*Ks[k][lane + 32*i];
        s = wsum(s);
        if (lane==0) E[q][k] += s;
      }
    }
    __syncthreads();
  }

  for (int q=warp; q<T_LEN; q+=8){
    float e = 0.f;
    if (lane < T_LEN){
      float bse = E[q][lane]*0.04419417382415922f + ((lane<=q)?1.f:0.f);
      e = __expf(bse);
      E[q][lane] = e;
    }
    float sc = e;
    #pragma unroll
    for (int o=1;o<32;o<<=1){
      float v = __shfl_up_sync(0xffffffffu, sc, o);
      if (lane >= o) sc += v;
    }
    if (lane < T_LEN) R[q][lane] = 1.f / sc;
  }
  __syncthreads();

  for (int t=warp; t<TM1; t+=8){
    if (lane <= t){
      float acc = 0.f;
      #pragma unroll 4
      for (int q=0; q<=t; q++) acc += E[q][lane]*R[q][t];
      g_wbar[(((t*BATCH)+b)*NH + h)*T_LEN + lane] = acc / (float)(t+1);
    }
  }
}

// ---------------- pooled context, split fused into epilogue ------------------
__global__ __launch_bounds__(128) void k_pctx(){
  const int t = blockIdx.x, b = blockIdx.y, h = blockIdx.z;
  __shared__ float w[T_LEN];
  const int tid = threadIdx.x;
  if (tid < T_LEN) w[tid] = (tid<=t) ? g_wbar[((t*BATCH+b)*NH+h)*T_LEN + tid] : 0.f;
  __syncthreads();
  float4 a = make_float4(0.f,0.f,0.f,0.f);
  for (int k=0;k<=t;k++){
    const float* vp = &g_qkv[((size_t)(k*BATCH+b))*(3*EDIM) + 2*EDIM + h*HDIM];
    float4 vv = *(const float4*)(vp + 4*tid);
    float wk = w[k];
    a.x += wk*vv.x; a.y += wk*vv.y; a.z += wk*vv.z; a.w += wk*vv.w;
  }
  const int row = t*BATCH + b;
  const int kp0 = h*256 + 2*tid;
  const int c   = kp0 >> 4;
  const int kk0 = kp0 & 15, kk1 = kk0 + 1;
  float rx, ry;
  uint32_t hi0 = pack_hi(a.x, a.y, rx, ry);
  uint32_t lo0 = pack_lo(rx, ry);
  uint32_t hi1 = pack_hi(a.z, a.w, rx, ry);
  uint32_t lo1 = pack_lo(rx, ry);
  size_t base = ((size_t)((row >> 7)*NCHUNK + c))*4096;
  int p0 = posw(row, kk0), p1 = posw(row, kk1);
  g_Asp2[base + p0] = hi0; g_Asp2[base + 2048 + p0] = lo0;
  g_Asp2[base + p1] = hi1; g_Asp2[base + 2048 + p1] = lo1;
}

// ---------------- head FC (sums split-K partials + bo) -----------------------
__global__ __launch_bounds__(256) void k_head(const float* __restrict__ Wfc,
                                              const float* __restrict__ bfc,
                                              const float* __restrict__ bo,
                                              float* __restrict__ out){
  const int t = blockIdx.x, b = blockIdx.y;
  __shared__ float P[EDIM];
  __shared__ float Wf[64][65];
  const int tid = threadIdx.x;
  const size_t rbase = ((size_t)(t*BATCH+b))*EDIM;
  for (int i=tid;i<EDIM;i+=256)
    P[i] = g_pooled[rbase + i] + g_pooled[(size_t)ROWS2*EDIM + rbase + i] + bo[i];
  for (int i=tid;i<4096;i+=256) Wf[i>>6][i&63] = Wfc[i];
  __syncthreads();
  #pragma unroll 4
  for (int u=0;u<16;u++){
    int idx = tid + 256*u;
    int f = idx >> 6, n = idx & 63;
    float s = bfc[n];
    #pragma unroll
    for (int j=0;j<64;j++) s += P[f*64+j]*Wf[n][j];
    out[(((size_t)(b*64+f))*T_LEN + (t+1))*64 + n] = fmaxf(s, 0.f);
  }
}

// ---------------- copy t=0 slice ---------------------------------------------
__global__ void k_copy0(const float* __restrict__ x, float* __restrict__ out){
  int i = blockIdx.x*blockDim.x + threadIdx.x;
  if (i >= BATCH*64*64) return;
  int n = i & 63, bf = i >> 6;
  size_t a = (size_t)bf*(T_LEN*64) + n;    // t = 0
  out[a] = x[a];
}

// ---------------- launch ------------------------------------------------------
extern "C" void kernel_launch(void* const* d_in, const int* in_sizes, int n_in,
                              void* d_out, int out_size){
  const float* x    = (const float*)d_in[0];
  const float* Wqkv = (const float*)d_in[1];
  const float* bqkv = (const float*)d_in[2];
  const float* Wo   = (const float*)d_in[3];
  const float* bo   = (const float*)d_in[4];
  const float* Wfc  = (const float*)d_in[5];
  const float* bfc  = (const float*)d_in[6];
  float* out = (float*)d_out;

  cudaFuncSetAttribute(gemm_tc, cudaFuncAttributeMaxDynamicSharedMemorySize, GEMM_SMEM);

  uint32_t *Asp1, *Bsp1, *Asp2, *Bsp2;
  float *qkv, *pooled;
  cudaGetSymbolAddress((void**)&Asp1, g_Asp1);
  cudaGetSymbolAddress((void**)&Bsp1, g_Bsp1);
  cudaGetSymbolAddress((void**)&Asp2, g_Asp2);
  cudaGetSymbolAddress((void**)&Bsp2, g_Bsp2);
  cudaGetSymbolAddress((void**)&qkv,    g_qkv);
  cudaGetSymbolAddress((void**)&pooled, g_pooled);

  k_splitx<<<(TB*1024 + 255)/256, 256>>>(x);                       // 0
  k_splitw<<<(12288*1024 + 255)/256, 256>>>(Wqkv, Bsp1, 12288);    // 1
  k_splitw<<<(4096*1024 + 255)/256, 256>>>(Wo, Bsp2, 4096);        // 2
  gemm_tc<<<dim3(3, 96, 1), 256, GEMM_SMEM>>>(Asp1, Bsp1, bqkv, qkv,
                                              3*EDIM, TB, NCHUNK, 0);          // 3
  k_attn<<<BATCH*NH, 256>>>();                                     // 4
  k_pctx<<<dim3(TM1, BATCH, NH), 128>>>();                         // 5
  gemm_tc<<<dim3(3, 32, 2), 256, GEMM_SMEM>>>(Asp2, Bsp2, nullptr, pooled,
                                              EDIM, ROWS2, NCHUNK/2, ROWS2*EDIM); // 6
  k_head<<<dim3(TM1, BATCH), 256>>>(Wfc, bfc, bo, out);            // 7
  k_copy0<<<(BATCH*64*64 + 255)/256, 256>>>(x, out);               // 8
}

// round 15
// speedup vs baseline: 1.5267x; 1.0185x over previous
#include <cuda_runtime.h>
#include <cuda_bf16.h>
#include <math.h>
#include <cstdint>

#define T_LEN 24
#define BATCH 16
#define NH    8
#define HDIM  512
#define EDIM  4096
#define TB    (T_LEN*BATCH)     /* 384  */
#define TM1   (T_LEN-1)         /* 23   */
#define ROWS2 (TM1*BATCH)       /* 368  */
#define GK    4096
#define KC    32
#define NCHUNK (GK/KC)          /* 128 small chunks */

// ---------------- scratch (static device globals; zero-init, no alloc) ------
__device__ uint32_t g_Asp1[3u*NCHUNK*4096];    // xt split      (6.3 MB)
__device__ uint32_t g_Bsp1[96u*NCHUNK*4096];   // Wqkv split    (201 MB)
__device__ uint32_t g_Asp2[3u*NCHUNK*4096];    // pctx split    (6.3 MB) pad rows stay 0
__device__ uint32_t g_Bsp2[32u*NCHUNK*4096];   // Wo split      (67 MB)
__device__ float    g_qkv[TB*3*EDIM];
__device__ float    g_pooled[2u*ROWS2*EDIM];   // two split-K partials
__device__ float    g_wbar[TM1*BATCH*NH*T_LEN];

// ---------------- layout helper (shared by writers and reader) ---------------
__device__ __forceinline__ int posw(int row, int kk){
  int s = kk >> 3, kb = kk & 7;
  int perm = (kb < 4) ? (2*kb) : (2*(kb-4) + 1);
  return ((row & 127) * 16) + 8*(s ^ ((row >> 1) & 1)) + perm;
}

__device__ __forceinline__ uint32_t pack_hi(float x, float y, float& rx, float& ry){
  __nv_bfloat16 hx = __float2bfloat16(x), hy = __float2bfloat16(y);
  rx = x - __bfloat162float(hx);
  ry = y - __bfloat162float(hy);
  return ((uint32_t)__bfloat16_as_ushort(hy) << 16) | __bfloat16_as_ushort(hx);
}
__device__ __forceinline__ uint32_t pack_lo(float rx, float ry){
  __nv_bfloat16 lx = __float2bfloat16(rx), ly = __float2bfloat16(ry);
  return ((uint32_t)__bfloat16_as_ushort(ly) << 16) | __bfloat16_as_ushort(lx);
}

// ---------------- split kernels (float4 per thread) --------------------------
__global__ __launch_bounds__(256) void k_splitw(const float* __restrict__ W,
                                                uint32_t* __restrict__ dst, int nrows){
  int idx = blockIdx.x*256 + threadIdx.x;          // float4 index
  if (idx >= nrows*1024) return;
  int row = idx >> 10, q = idx & 1023;
  float4 v = *(const float4*)(W + (size_t)row*GK + 4*q);
  int kk0 = (2*q) & 15, c = q >> 3;
  float rx, ry, rz, rw;
  uint32_t hi0 = pack_hi(v.x, v.y, rx, ry);
  uint32_t hi1 = pack_hi(v.z, v.w, rz, rw);
  uint32_t lo0 = pack_lo(rx, ry);
  uint32_t lo1 = pack_lo(rz, rw);
  size_t base = ((size_t)((row >> 7)*NCHUNK + c))*4096;
  int p0 = posw(row, kk0), p1 = posw(row, kk0+1);
  dst[base + p0] = hi0;        dst[base + p1] = hi1;
  dst[base + 2048 + p0] = lo0; dst[base + 2048 + p1] = lo1;
}

__global__ __launch_bounds__(256) void k_splitx(const float* __restrict__ x){
  int idx = blockIdx.x*256 + threadIdx.x;          // float4 index
  if (idx >= TB*1024) return;
  int row = idx >> 10, q = idx & 1023;
  int t = row >> 4, b = row & 15;
  int e = 4*q, f = e >> 6, n = e & 63;
  float4 v = *(const float4*)(x + (((size_t)(b*64 + f))*T_LEN + t)*64 + n);
  int kk0 = (2*q) & 15, c = q >> 3;
  float rx, ry, rz, rw;
  uint32_t hi0 = pack_hi(v.x, v.y, rx, ry);
  uint32_t hi1 = pack_hi(v.z, v.w, rz, rw);
  uint32_t lo0 = pack_lo(rx, ry);
  uint32_t lo1 = pack_lo(rz, rw);
  size_t base = ((size_t)((row >> 7)*NCHUNK + c))*4096;
  int p0 = posw(row, kk0), p1 = posw(row, kk0+1);
  g_Asp1[base + p0] = hi0;        g_Asp1[base + p1] = hi1;
  g_Asp1[base + 2048 + p0] = lo0; g_Asp1[base + 2048 + p1] = lo1;
}

// ---------------- cp.async helpers -------------------------------------------
__device__ __forceinline__ uint32_t smem_u32(const void* p){
  uint32_t a;
  asm("{ .reg .u64 t; cvta.to.shared.u64 t, %1; cvt.u32.u64 %0, t; }" : "=r"(a) : "l"(p));
  return a;
}
__device__ __forceinline__ void cpa16(uint32_t s, const void* g){
  asm volatile("cp.async.cg.shared.global [%0], [%1], 16;" :: "r"(s), "l"(g));
}
__device__ __forceinline__ void cpa_commit(){
  asm volatile("cp.async.commit_group;" ::: "memory");
}
__device__ __forceinline__ void cpa_wait1(){
  asm volatile("cp.async.wait_group 1;" ::: "memory");
}

// ---------------- mma.sync wrapper -------------------------------------------
__device__ __forceinline__ void mma16816(float* c,
                                         uint32_t a0, uint32_t a1, uint32_t a2, uint32_t a3,
                                         uint32_t b0, uint32_t b1){
  asm volatile(
    "mma.sync.aligned.m16n8k16.row.col.f32.bf16.bf16.f32 "
    "{%0,%1,%2,%3}, {%4,%5,%6,%7}, {%8,%9}, {%0,%1,%2,%3};"
    : "+f"(c[0]), "+f"(c[1]), "+f"(c[2]), "+f"(c[3])
    : "r"(a0), "r"(a1), "r"(a2), "r"(a3), "r"(b0), "r"(b1));
}

// ---------------- GEMM: C(M,Nn) = A @ B^T (+bias) (pre-split operands) -------
// Big stage = TWO 32-wide K-chunks = 2 x [Ahi 8K|Alo 8K|Bhi 8K|Blo 8K] = 64KB.
// 3 stages = 192KB (1 CTA/SM). Barriers per GEMM: nchunks/2.
#define SUB_B    32768
#define STAGE_B  65536
#define NSTAGE   3
#define GEMM_SMEM (NSTAGE*STAGE_B)

__global__ __launch_bounds__(256,1) void gemm_tc(const uint32_t* __restrict__ Asp,
                                                 const uint32_t* __restrict__ Bsp,
                                                 const float* __restrict__ bias,
                                                 float* __restrict__ C,
                                                 int Nn, int Mvalid,
                                                 int nchunks, int zstride){
  extern __shared__ char smem[];
  const uint32_t sb = smem_u32(smem);
  const int tid = threadIdx.x, warp = tid >> 5, lane = tid & 31;
  const int g = lane >> 2, tg = lane & 3;
  const int wm = warp >> 2, wn = warp & 3;
  const int R0 = wm*64, N0 = wn*32;
  const int X = (g >> 1) & 1;
  const int z = blockIdx.z;
  const int koff = z * nchunks;                 // small-chunk offset of K-split
  const uint4* Ag = (const uint4*)(Asp) + ((size_t)blockIdx.x*NCHUNK + koff)*1024;
  const uint4* Bg = (const uint4*)(Bsp) + ((size_t)blockIdx.y*NCHUNK + koff)*1024;
  const float* bp = (z == 0) ? bias : nullptr;
  float* Cz = C + (size_t)z*zstride;
  const int nbig = nchunks >> 1;

  float acc[4][4][4];
  #pragma unroll
  for (int i=0;i<4;i++)
    #pragma unroll
    for (int j=0;j<4;j++)
      #pragma unroll
      for (int r=0;r<4;r++) acc[i][j][r] = 0.f;

  // load big-chunk bc (2 small chunks) into stage st
  auto issue = [&](int st, int bc){
    uint32_t dA = sb + st*STAGE_B + tid*16;
    const uint4* a = Ag + (size_t)(2*bc)*1024 + tid;
    const uint4* b = Bg + (size_t)(2*bc)*1024 + tid;
    #pragma unroll
    for (int h=0; h<2; h++){
      #pragma unroll
      for (int u=0;u<4;u++){
        cpa16(dA + h*SUB_B +         u*4096, a + h*1024 + u*256);
        cpa16(dA + h*SUB_B + 16384 + u*4096, b + h*1024 + u*256);
      }
    }
  };

  issue(0,0); cpa_commit();
  issue(1,1); cpa_commit();

  const uint32_t pbs0 = (uint32_t)(8*(0^X) + 2*tg)*4;
  const uint32_t pbs1 = (uint32_t)(8*(1^X) + 2*tg)*4;

  int st = 0;
  for (int bc = 0; bc < nbig; bc++){
    cpa_wait1();               // big-chunk bc resident (bc+1 may be in flight)
    __syncthreads();           // all warps done with stage (bc+2)%3 from pass bc-1
    if (bc+2 < nbig){
      int ns = st + 2; if (ns >= NSTAGE) ns -= NSTAGE;   // (st+2) mod 3
      issue(ns, bc+2);
    }
    cpa_commit();

    #pragma unroll
    for (int h=0; h<2; h++){
      const char* wb = smem + st*STAGE_B + h*SUB_B;
      #pragma unroll
      for (int s=0;s<2;s++){
        const uint32_t pb = s ? pbs1 : pbs0;
        uint2 bh[4], bl[4];
        #pragma unroll
        for (int j=0;j<4;j++){
          int n = N0 + 8*j + g;
          bh[j] = *(const uint2*)(wb + 16384 + n*64 + pb);
          bl[j] = *(const uint2*)(wb + 24576 + n*64 + pb);
        }
        #pragma unroll
        for (int i=0;i<4;i++){
          int r0 = R0 + 16*i + g;
          uint2 ah0 = *(const uint2*)(wb        + r0*64       + pb);
          uint2 ah1 = *(const uint2*)(wb        + r0*64 + 512 + pb);
          uint2 al0 = *(const uint2*)(wb + 8192 + r0*64       + pb);
          uint2 al1 = *(const uint2*)(wb + 8192 + r0*64 + 512 + pb);
          #pragma unroll
          for (int j=0;j<4;j++){
            mma16816(acc[i][j], ah0.x, ah1.x, ah0.y, ah1.y, bh[j].x, bh[j].y);
            mma16816(acc[i][j], ah0.x, ah1.x, ah0.y, ah1.y, bl[j].x, bl[j].y);
            mma16816(acc[i][j], al0.x, al1.x, al0.y, al1.y, bh[j].x, bh[j].y);
          }
        }
      }
    }
    st = (st+1 == NSTAGE) ? 0 : st+1;
  }

  const int bm = blockIdx.x*128, bn = blockIdx.y*128;
  #pragma unroll
  for (int i=0;i<4;i++){
    int row0 = bm + R0 + 16*i + g;
    int row1 = row0 + 8;
    #pragma unroll
    for (int j=0;j<4;j++){
      int col = bn + N0 + 8*j + 2*tg;
      float b0 = bp ? bp[col]   : 0.f;
      float b1 = bp ? bp[col+1] : 0.f;
      if (row0 < Mvalid){
        float2 o; o.x = acc[i][j][0] + b0; o.y = acc[i][j][1] + b1;
        *(float2*)&Cz[(size_t)row0*Nn + col] = o;
      }
      if (row1 < Mvalid){
        float2 o; o.x = acc[i][j][2] + b0; o.y = acc[i][j][3] + b1;
        *(float2*)&Cz[(size_t)row1*Nn + col] = o;
      }
    }
  }
}

// ---------------- small helpers ---------------------------------------------
__device__ __forceinline__ float wsum(float v){
  #pragma unroll
  for (int o=16;o;o>>=1) v += __shfl_xor_sync(0xffffffffu, v, o);
  return v;
}

// ---------------- attention --------------------------------------------------
__global__ __launch_bounds__(256) void k_attn(){
  const int b = blockIdx.x >> 3, h = blockIdx.x & 7;
  __shared__ float Ks[T_LEN][257];
  __shared__ float E[T_LEN][T_LEN+1];
  __shared__ float R[T_LEN][T_LEN+1];
  const int tid = threadIdx.x, warp = tid>>5, lane = tid&31;

  for (int i=tid;i<T_LEN*T_LEN;i+=256) E[i/T_LEN][i%T_LEN] = 0.f;
  __syncthreads();

  for (int c=0;c<2;c++){
    for (int i=tid;i<T_LEN*256;i+=256){
      int k=i>>8, d=i&255;
      Ks[k][d] = g_qkv[((size_t)(k*BATCH+b))*(3*EDIM) + EDIM + h*HDIM + c*256 + d];
    }
    __syncthreads();
    for (int q=warp; q<T_LEN; q+=8){
      const float* qp = &g_qkv[((size_t)(q*BATCH+b))*(3*EDIM) + h*HDIM + c*256];
      float qr[8];
      #pragma unroll
      for (int i=0;i<8;i++) qr[i] = qp[lane + 32*i];
      #pragma unroll 4
      for (int k=0;k<T_LEN;k++){
        float s = 0.f;
        #pragma unroll
        for (int i=0;i<8;i++) s += qr[i]*Ks[k][lane + 32*i];
        s = wsum(s);
        if (lane==0) E[q][k] += s;
      }
    }
    __syncthreads();
  }

  for (int q=warp; q<T_LEN; q+=8){
    float e = 0.f;
    if (lane < T_LEN){
      float bse = E[q][lane]*0.04419417382415922f + ((lane<=q)?1.f:0.f);
      e = __expf(bse);
      E[q][lane] = e;
    }
    float sc = e;
    #pragma unroll
    for (int o=1;o<32;o<<=1){
      float v = __shfl_up_sync(0xffffffffu, sc, o);
      if (lane >= o) sc += v;
    }
    if (lane < T_LEN) R[q][lane] = 1.f / sc;
  }
  __syncthreads();

  for (int t=warp; t<TM1; t+=8){
    if (lane <= t){
      float acc = 0.f;
      #pragma unroll 4
      for (int q=0; q<=t; q++) acc += E[q][lane]*R[q][t];
      g_wbar[(((t*BATCH)+b)*NH + h)*T_LEN + lane] = acc / (float)(t+1);
    }
  }
}

// ---------------- pooled context, split fused into epilogue ------------------
__global__ __launch_bounds__(128) void k_pctx(){
  const int t = blockIdx.x, b = blockIdx.y, h = blockIdx.z;
  __shared__ float w[T_LEN];
  const int tid = threadIdx.x;
  if (tid < T_LEN) w[tid] = (tid<=t) ? g_wbar[((t*BATCH+b)*NH+h)*T_LEN + tid] : 0.f;
  __syncthreads();
  float4 a = make_float4(0.f,0.f,0.f,0.f);
  for (int k=0;k<=t;k++){
    const float* vp = &g_qkv[((size_t)(k*BATCH+b))*(3*EDIM) + 2*EDIM + h*HDIM];
    float4 vv = *(const float4*)(vp + 4*tid);
    float wk = w[k];
    a.x += wk*vv.x; a.y += wk*vv.y; a.z += wk*vv.z; a.w += wk*vv.w;
  }
  const int row = t*BATCH + b;
  const int kp0 = h*256 + 2*tid;
  const int c   = kp0 >> 4;
  const int kk0 = kp0 & 15, kk1 = kk0 + 1;
  float rx, ry;
  uint32_t hi0 = pack_hi(a.x, a.y, rx, ry);
  uint32_t lo0 = pack_lo(rx, ry);
  uint32_t hi1 = pack_hi(a.z, a.w, rx, ry);
  uint32_t lo1 = pack_lo(rx, ry);
  size_t base = ((size_t)((row >> 7)*NCHUNK + c))*4096;
  int p0 = posw(row, kk0), p1 = posw(row, kk1);
  g_Asp2[base + p0] = hi0; g_Asp2[base + 2048 + p0] = lo0;
  g_Asp2[base + p1] = hi1; g_Asp2[base + 2048 + p1] = lo1;
}

// ---------------- head FC (sums split-K partials + bo) -----------------------
__global__ __launch_bounds__(256) void k_head(const float* __restrict__ Wfc,
                                              const float* __restrict__ bfc,
                                              const float* __restrict__ bo,
                                              float* __restrict__ out){
  const int t = blockIdx.x, b = blockIdx.y;
  __shared__ float P[EDIM];
  __shared__ float Wf[64][65];
  const int tid = threadIdx.x;
  const size_t rbase = ((size_t)(t*BATCH+b))*EDIM;
  for (int i=tid;i<EDIM;i+=256)
    P[i] = g_pooled[rbase + i] + g_pooled[(size_t)ROWS2*EDIM + rbase + i] + bo[i];
  for (int i=tid;i<4096;i+=256) Wf[i>>6][i&63] = Wfc[i];
  __syncthreads();
  #pragma unroll 4
  for (int u=0;u<16;u++){
    int idx = tid + 256*u;
    int f = idx >> 6, n = idx & 63;
    float s = bfc[n];
    #pragma unroll
    for (int j=0;j<64;j++) s += P[f*64+j]*Wf[n][j];
    out[(((size_t)(b*64+f))*T_LEN + (t+1))*64 + n] = fmaxf(s, 0.f);
  }
}

// ---------------- copy t=0 slice ---------------------------------------------
__global__ void k_copy0(const float* __restrict__ x, float* __restrict__ out){
  int i = blockIdx.x*blockDim.x + threadIdx.x;
  if (i >= BATCH*64*64) return;
  int n = i & 63, bf = i >> 6;
  size_t a = (size_t)bf*(T_LEN*64) + n;    // t = 0
  out[a] = x[a];
}

// ---------------- launch ------------------------------------------------------
extern "C" void kernel_launch(void* const* d_in, const int* in_sizes, int n_in,
                              void* d_out, int out_size){
  const float* x    = (const float*)d_in[0];
  const float* Wqkv = (const float*)d_in[1];
  const float* bqkv = (const float*)d_in[2];
  const float* Wo   = (const float*)d_in[3];
  const float* bo   = (const float*)d_in[4];
  const float* Wfc  = (const float*)d_in[5];
  const float* bfc  = (const float*)d_in[6];
  float* out = (float*)d_out;

  cudaFuncSetAttribute(gemm_tc, cudaFuncAttributeMaxDynamicSharedMemorySize, GEMM_SMEM);

  uint32_t *Asp1, *Bsp1, *Asp2, *Bsp2;
  float *qkv, *pooled;
  cudaGetSymbolAddress((void**)&Asp1, g_Asp1);
  cudaGetSymbolAddress((void**)&Bsp1, g_Bsp1);
  cudaGetSymbolAddress((void**)&Asp2, g_Asp2);
  cudaGetSymbolAddress((void**)&Bsp2, g_Bsp2);
  cudaGetSymbolAddress((void**)&qkv,    g_qkv);
  cudaGetSymbolAddress((void**)&pooled, g_pooled);

  k_splitx<<<(TB*1024 + 255)/256, 256>>>(x);                       // 0
  k_splitw<<<(12288*1024 + 255)/256, 256>>>(Wqkv, Bsp1, 12288);    // 1
  k_splitw<<<(4096*1024 + 255)/256, 256>>>(Wo, Bsp2, 4096);        // 2
  gemm_tc<<<dim3(3, 96, 1), 256, GEMM_SMEM>>>(Asp1, Bsp1, bqkv, qkv,
                                              3*EDIM, TB, NCHUNK, 0);          // 3
  k_attn<<<BATCH*NH, 256>>>();                                     // 4
  k_pctx<<<dim3(TM1, BATCH, NH), 128>>>();                         // 5
  gemm_tc<<<dim3(3, 32, 2), 256, GEMM_SMEM>>>(Asp2, Bsp2, nullptr, pooled,
                                              EDIM, ROWS2, NCHUNK/2, ROWS2*EDIM); // 6
  k_head<<<dim3(TM1, BATCH), 256>>>(Wfc, bfc, bo, out);            // 7
  k_copy0<<<(BATCH*64*64 + 255)/256, 256>>>(x, out);               // 8
}